// round 1
// baseline (speedup 1.0000x reference)
#include <cuda_runtime.h>

// ---------------------------------------------------------------------------
// NaiveAttention: out = softmax((xWq+bq)(xWk+bk)^T * C^-0.5) (xWv+bv) Wo + bo
// B=4, N=4096, C=1024 fp32.
// Round 0: tiled SIMT fp32 GEMM pipeline (baseline for tensor-core port).
// ---------------------------------------------------------------------------

#define BM 128
#define BN 128
#define BK 8
#define TM 8
#define TN 8

// Scratch (device globals — no allocation allowed in kernel_launch).
__device__ float g_q [16777216];            // [4,4096,1024]
__device__ float g_k [16777216];
__device__ float g_v [16777216];
__device__ float g_s [67108864];            // [4,4096,4096] scores / attn
__device__ float g_ao[16777216];            // attn @ v

// ---------------------------------------------------------------------------
// Batched tiled GEMM.
//  C[z] = A[z] @ B[z] (+ bias),  A: [M,K] row-major.
//  TRANS_B=false: B is [K,N] row-major.
//  TRANS_B=true : B is [N,K] row-major (C[i][j] = sum_k A[i,k]*B[j,k]).
// All of M,N divisible by 128; K divisible by 8.
// ---------------------------------------------------------------------------
template <bool TRANS_B, bool HAS_BIAS>
__global__ __launch_bounds__(256, 2)
void gemm_k(const float* __restrict__ A, const float* __restrict__ B,
            const float* __restrict__ bias, float* __restrict__ C,
            int M, int N, int K,
            long long sA, long long sB, long long sC)
{
    __shared__ float As[BK][BM];
    __shared__ float Bs[BK][BN];

    A += (long long)blockIdx.z * sA;
    B += (long long)blockIdx.z * sB;
    C += (long long)blockIdx.z * sC;

    const int tid = threadIdx.x;
    const int m0  = blockIdx.y * BM;
    const int n0  = blockIdx.x * BN;
    const int ty  = tid >> 4;      // 0..15
    const int tx  = tid & 15;      // 0..15

    // A tile loader: 128 rows x 8 cols, one float4 per thread.
    const int aRow = tid >> 1;           // 0..127
    const int aCol = (tid & 1) * 4;      // 0 or 4
    // B tile loader (normal): 8 rows x 128 cols.
    const int bRowN = tid >> 5;          // 0..7
    const int bColN = (tid & 31) * 4;    // 0..124

    float acc[TM][TN] = {};

    for (int k0 = 0; k0 < K; k0 += BK) {
        // load A tile (transposed into smem: As[k][m])
        float4 av = *reinterpret_cast<const float4*>(
            &A[(long long)(m0 + aRow) * K + (k0 + aCol)]);
        As[aCol + 0][aRow] = av.x;
        As[aCol + 1][aRow] = av.y;
        As[aCol + 2][aRow] = av.z;
        As[aCol + 3][aRow] = av.w;

        if (TRANS_B) {
            // B[N,K]: load 128 n-rows x 8 k-cols, store Bs[k][n]
            float4 bv = *reinterpret_cast<const float4*>(
                &B[(long long)(n0 + aRow) * K + (k0 + aCol)]);
            Bs[aCol + 0][aRow] = bv.x;
            Bs[aCol + 1][aRow] = bv.y;
            Bs[aCol + 2][aRow] = bv.z;
            Bs[aCol + 3][aRow] = bv.w;
        } else {
            // B[K,N]: load 8 k-rows x 128 n-cols directly
            float4 bv = *reinterpret_cast<const float4*>(
                &B[(long long)(k0 + bRowN) * N + (n0 + bColN)]);
            Bs[bRowN][bColN + 0] = bv.x;
            Bs[bRowN][bColN + 1] = bv.y;
            Bs[bRowN][bColN + 2] = bv.z;
            Bs[bRowN][bColN + 3] = bv.w;
        }
        __syncthreads();

        #pragma unroll
        for (int kk = 0; kk < BK; kk++) {
            float ra[TM], rb[TN];
            #pragma unroll
            for (int i = 0; i < TM; i++) ra[i] = As[kk][ty * TM + i];
            #pragma unroll
            for (int j = 0; j < TN; j++) rb[j] = Bs[kk][tx * TN + j];
            #pragma unroll
            for (int i = 0; i < TM; i++)
                #pragma unroll
                for (int j = 0; j < TN; j++)
                    acc[i][j] = fmaf(ra[i], rb[j], acc[i][j]);
        }
        __syncthreads();
    }

    // epilogue: two float4 stores per row
    #pragma unroll
    for (int i = 0; i < TM; i++) {
        const long long row = m0 + ty * TM + i;
        float* cp = &C[row * N + n0 + tx * TN];
        float4 o0, o1;
        o0.x = acc[i][0]; o0.y = acc[i][1]; o0.z = acc[i][2]; o0.w = acc[i][3];
        o1.x = acc[i][4]; o1.y = acc[i][5]; o1.z = acc[i][6]; o1.w = acc[i][7];
        if (HAS_BIAS) {
            const float* bp = &bias[n0 + tx * TN];
            o0.x += bp[0]; o0.y += bp[1]; o0.z += bp[2]; o0.w += bp[3];
            o1.x += bp[4]; o1.y += bp[5]; o1.z += bp[6]; o1.w += bp[7];
        }
        reinterpret_cast<float4*>(cp)[0] = o0;
        reinterpret_cast<float4*>(cp)[1] = o1;
    }
}

// ---------------------------------------------------------------------------
// Row softmax over rows of length 4096 with pre-scale:
//   row <- softmax(scale * row)
// One block (256 threads) per row; 16 elements/thread held in registers.
// ---------------------------------------------------------------------------
__global__ __launch_bounds__(256)
void softmax_k(float* __restrict__ S, float scale)
{
    float* row = S + (long long)blockIdx.x * 4096;
    const int t = threadIdx.x;
    __shared__ float red[256];

    float vals[16];
    float m = -1e30f;
    #pragma unroll
    for (int i = 0; i < 16; i++) {
        vals[i] = row[t + i * 256];
        m = fmaxf(m, vals[i]);
    }
    red[t] = m;
    __syncthreads();
    #pragma unroll
    for (int s = 128; s > 0; s >>= 1) {
        if (t < s) red[t] = fmaxf(red[t], red[t + s]);
        __syncthreads();
    }
    m = red[0];
    __syncthreads();

    float sum = 0.f;
    #pragma unroll
    for (int i = 0; i < 16; i++) {
        vals[i] = __expf(scale * (vals[i] - m));
        sum += vals[i];
    }
    red[t] = sum;
    __syncthreads();
    #pragma unroll
    for (int s = 128; s > 0; s >>= 1) {
        if (t < s) red[t] += red[t + s];
        __syncthreads();
    }
    const float inv = 1.0f / red[0];
    #pragma unroll
    for (int i = 0; i < 16; i++)
        row[t + i * 256] = vals[i] * inv;
}

// ---------------------------------------------------------------------------
extern "C" void kernel_launch(void* const* d_in, const int* in_sizes, int n_in,
                              void* d_out, int out_size)
{
    const float* x  = (const float*)d_in[0];
    const float* Wq = (const float*)d_in[1];
    const float* bq = (const float*)d_in[2];
    const float* Wk = (const float*)d_in[3];
    const float* bk = (const float*)d_in[4];
    const float* Wv = (const float*)d_in[5];
    const float* bv = (const float*)d_in[6];
    const float* Wo = (const float*)d_in[7];
    const float* bo = (const float*)d_in[8];
    float* out = (float*)d_out;

    const int C    = 1024;
    const int Nseq = 4096;
    const int M    = in_sizes[0] / C;   // B * Nseq = 16384
    const int Bb   = M / Nseq;          // 4
    const float scale = 0.03125f;       // 1024^-0.5

    float *q, *k, *v, *s, *ao;
    cudaGetSymbolAddress((void**)&q,  g_q);
    cudaGetSymbolAddress((void**)&k,  g_k);
    cudaGetSymbolAddress((void**)&v,  g_v);
    cudaGetSymbolAddress((void**)&s,  g_s);
    cudaGetSymbolAddress((void**)&ao, g_ao);

    const long long qkvStride  = (long long)Nseq * C;      // per-batch q/k/v
    const long long sStride    = (long long)Nseq * Nseq;   // per-batch scores

    dim3 blk(256);

    // 1) q,k,v projections: [16384,1024] @ [1024,1024] + bias
    {
        dim3 grd(C / BN, M / BM, 1);
        gemm_k<false, true><<<grd, blk>>>(x, Wq, bq, q, M, C, C, 0, 0, 0);
        gemm_k<false, true><<<grd, blk>>>(x, Wk, bk, k, M, C, C, 0, 0, 0);
        gemm_k<false, true><<<grd, blk>>>(x, Wv, bv, v, M, C, C, 0, 0, 0);
    }

    // 2) scores[b] = q[b] @ k[b]^T : [4096,4096,K=1024], batched
    {
        dim3 grd(Nseq / BN, Nseq / BM, Bb);
        gemm_k<true, false><<<grd, blk>>>(q, k, nullptr, s,
                                          Nseq, Nseq, C,
                                          qkvStride, qkvStride, sStride);
    }

    // 3) row softmax with scale
    softmax_k<<<M, blk>>>(s, scale);

    // 4) ao[b] = attn[b] @ v[b] : [4096,1024,K=4096], batched
    {
        dim3 grd(C / BN, Nseq / BM, Bb);
        gemm_k<false, false><<<grd, blk>>>(s, v, nullptr, ao,
                                           Nseq, C, Nseq,
                                           sStride, qkvStride, qkvStride);
    }

    // 5) out = ao @ Wo + bo
    {
        dim3 grd(C / BN, M / BM, 1);
        gemm_k<false, true><<<grd, blk>>>(ao, Wo, bo, out, M, C, C, 0, 0, 0);
    }
}

// round 6
// speedup vs baseline: 4.3777x; 4.3777x over previous
#include <cuda_runtime.h>
#include <cuda_bf16.h>
#include <cstdint>

// ---------------------------------------------------------------------------
// NaiveAttention on GB300. B=4, N=4096, C=1024 fp32.
// Dual-target build:
//   sm_103a (arch-specific) pass -> tcgen05 bf16 3-split (Markidis) GEMM
//   base sm_103 pass             -> SIMT fp32 tiled GEMM (proven R0 body)
// Same kernel signatures/launch config in both, so host code is shared.
// ---------------------------------------------------------------------------

#if !defined(__CUDA_ARCH__)
#define USE_TC 1    // host pass: body choice irrelevant
#elif defined(__CUDA_ARCH_FEAT_SM103_ALL) || defined(__CUDA_ARCH_FEAT_SM100_ALL) || \
      defined(__CUDA_ARCH_FEAT_SM101_ALL) || defined(__CUDA_ARCH_SPECIFIC__) || \
      defined(__CUDA_ARCH_FAMILY_SPECIFIC__)
#define USE_TC 1    // arch/family-specific pass: tcgen05 available
#else
#define USE_TC 0    // base target: no tcgen05 text may appear
#endif

#define DIMC 1024
#define NSEQ 4096
#define NB   4

// Scratch (device globals — no allocation allowed).
__device__ float g_q [NB*NSEQ*DIMC];
__device__ float g_k [NB*NSEQ*DIMC];
__device__ float g_v [NB*NSEQ*DIMC];
__device__ float g_vt[NB*DIMC*NSEQ];
__device__ float g_s [67108864];          // [4,4096,4096]
__device__ float g_ao[NB*NSEQ*DIMC];
__device__ float g_wt[4*DIMC*DIMC];       // WqT, WkT, WvT, WoT

#define KT 64
#define IDESC 0x8200490u   // f32 accum, bf16 x bf16, M=128, N=128
#define BUF_BYTES 65536    // Ahi(16K) Alo(16K) Bhi(16K) Blo(16K)
#define SMEM_BYTES (2048 + 2 * BUF_BYTES)

#if USE_TC
// ---------------------------------------------------------------------------
// PTX helpers (sm_103a only — never compiled for the base target)
// ---------------------------------------------------------------------------
__device__ __forceinline__ uint32_t smem_u32(const void* p) {
    uint32_t a;
    asm("{ .reg .u64 t; cvta.to.shared.u64 t, %1; cvt.u32.u64 %0, t; }"
        : "=r"(a) : "l"(p));
    return a;
}

#define MBAR_INIT(addr, cnt) \
    asm volatile("mbarrier.init.shared.b64 [%0], %1;" :: "r"(addr), "r"(cnt) : "memory")

#define MBAR_WAIT(addr, ph) do {                                              \
    uint32_t _m = (addr); uint32_t _p = (ph); uint32_t _done;                 \
    asm volatile("{\n\t.reg .pred p;\n\t"                                     \
        "mbarrier.try_wait.parity.acquire.cta.shared::cta.b64 p, [%1], %2;\n\t" \
        "selp.b32 %0, 1, 0, p;\n\t}"                                          \
        : "=r"(_done) : "r"(_m), "r"(_p) : "memory");                         \
    if (!_done) {                                                             \
        asm volatile("{\n\t.reg .pred P1;\n\t"                                \
            "WL_%=:\n\t"                                                      \
            "mbarrier.try_wait.parity.acquire.cta.shared::cta.b64 P1, [%0], %1, 0x989680;\n\t" \
            "@P1 bra.uni WD_%=;\n\t"                                          \
            "bra.uni WL_%=;\n\t"                                              \
            "WD_%=:\n\t}"                                                     \
            :: "r"(_m), "r"(_p) : "memory");                                  \
    }                                                                         \
} while (0)

#define TC_ALLOC(sm, n)   asm volatile("tcgen05.alloc.cta_group::1.sync.aligned.shared::cta.b32 [%0], %1;" :: "r"(sm), "r"(n) : "memory")
#define TC_DEALLOC(t, n)  asm volatile("tcgen05.dealloc.cta_group::1.sync.aligned.b32 %0, %1;" :: "r"(t), "r"(n))
#define TC_RELINQ()       asm volatile("tcgen05.relinquish_alloc_permit.cta_group::1.sync.aligned;")
#define TC_COMMIT(mb)     asm volatile("tcgen05.commit.cta_group::1.mbarrier::arrive::one.shared::cluster.b64 [%0];" :: "r"(mb) : "memory")
#define TC_FENCE_AFTER()  asm volatile("tcgen05.fence::after_thread_sync;" ::: "memory")
#define TC_FENCE_BEFORE() asm volatile("tcgen05.fence::before_thread_sync;" ::: "memory")
#define TC_WAIT_LD()      asm volatile("tcgen05.wait::ld.sync.aligned;" ::: "memory")
#define FENCE_ASYNC()     asm volatile("fence.proxy.async.shared::cta;" ::: "memory")

#define TC_LD_X32(r, a) \
    asm volatile("tcgen05.ld.sync.aligned.32x32b.x32.b32 " \
        "{%0, %1, %2, %3, %4, %5, %6, %7, %8, %9, %10, %11, %12, %13, %14, %15, " \
        " %16, %17, %18, %19, %20, %21, %22, %23, %24, %25, %26, %27, %28, %29, %30, %31}, [%32];" \
        : "=r"((r)[0]), "=r"((r)[1]), "=r"((r)[2]), "=r"((r)[3]), \
          "=r"((r)[4]), "=r"((r)[5]), "=r"((r)[6]), "=r"((r)[7]), \
          "=r"((r)[8]), "=r"((r)[9]), "=r"((r)[10]), "=r"((r)[11]), \
          "=r"((r)[12]), "=r"((r)[13]), "=r"((r)[14]), "=r"((r)[15]), \
          "=r"((r)[16]), "=r"((r)[17]), "=r"((r)[18]), "=r"((r)[19]), \
          "=r"((r)[20]), "=r"((r)[21]), "=r"((r)[22]), "=r"((r)[23]), \
          "=r"((r)[24]), "=r"((r)[25]), "=r"((r)[26]), "=r"((r)[27]), \
          "=r"((r)[28]), "=r"((r)[29]), "=r"((r)[30]), "=r"((r)[31]) \
        : "r"(a))

__device__ __forceinline__ void mma_f16_ss(uint32_t d, uint64_t a, uint64_t b,
                                           uint32_t idesc, uint32_t en) {
    asm volatile("{\n\t.reg .pred p;\n\tsetp.ne.u32 p, %4, 0;\n\t"
        "tcgen05.mma.cta_group::1.kind::f16 [%0], %1, %2, %3, {%5, %5, %5, %5}, p;\n\t}"
        :: "r"(d), "l"(a), "l"(b), "r"(idesc), "r"(en), "r"(0u) : "memory");
}

__device__ __forceinline__ uint64_t mk_desc(uint32_t addr) {
    const uint64_t base = (uint64_t(2) << 61) | (uint64_t(1) << 46)
                        | (uint64_t(64) << 32) | (uint64_t(1) << 16);
    return base | ((uint64_t)(addr >> 4) & 0x3FFF);
}

// pack two f32 -> bf16x2 (lo goes to low half)
__device__ __forceinline__ uint32_t pack_bf16(float lo, float hi) {
    uint32_t r;
    asm("cvt.rn.satfinite.bf16x2.f32 %0, %1, %2;" : "=r"(r) : "f"(hi), "f"(lo));
    return r;
}
__device__ __forceinline__ float bf16_rn_f32(float x) {
    uint32_t r;
    asm("cvt.rn.satfinite.bf16x2.f32 %0, %1, %1;" : "=r"(r) : "f"(x));
    return __uint_as_float(r << 16);
}
#endif  // USE_TC

// ---------------------------------------------------------------------------
// GEMM:  C[z] = A[z] @ B[z]^T (+ bias)
//   A: [M,K] fp32 row-major, B: [N,K] fp32 row-major, C: [M,N] fp32.
//   128x128 CTA tile, 256 threads. M,N % 128 == 0, K % 64 == 0.
// ---------------------------------------------------------------------------
template <bool HAS_BIAS>
__global__ __launch_bounds__(256, 1)
void tc_gemm(const float* __restrict__ A, const float* __restrict__ B,
             const float* __restrict__ bias, float* __restrict__ Cout,
             int M, int N, int K,
             long long sA, long long sB, long long sC)
{
    extern __shared__ char smem[];

    A    += (long long)blockIdx.z * sA;
    B    += (long long)blockIdx.z * sB;
    Cout += (long long)blockIdx.z * sC;

    const int tid = threadIdx.x;
    const int m0  = blockIdx.y * 128;
    const int n0  = blockIdx.x * 128;

#if USE_TC
    // ======================= tcgen05 bf16 3-split path ======================
    const uint32_t sb    = smem_u32(smem);
    const uint32_t tiles = (sb + 32 + 1023) & ~1023u;   // 1KB-aligned tile region
    char* tilesg = smem + (tiles - sb);
    const uint32_t mbar0 = sb;
    const uint32_t mbar1 = sb + 8;
    const uint32_t tptr  = sb + 16;

    if (tid < 32) TC_ALLOC(tptr, 128);
    if (tid == 0) { MBAR_INIT(mbar0, 1); MBAR_INIT(mbar1, 1); }
    __syncthreads();
    uint32_t tmem;
    asm volatile("ld.shared.b32 %0, [%1];" : "=r"(tmem) : "r"(tptr));

    const int nk = K / KT;
    int ph0 = 0, ph1 = 0;

    for (int t = 0; t < nk; t++) {
        const int buf = t & 1;
        const uint32_t bb = tiles + buf * BUF_BYTES;

        if (t >= 2) {
            if (buf == 0) { MBAR_WAIT(mbar0, ph0); ph0 ^= 1; }
            else          { MBAR_WAIT(mbar1, ph1); ph1 ^= 1; }
        }

        // ---- load + split A tile: 128 rows x 64 k (fp32 -> bf16 hi/lo) ----
        const float* Ag = A + (long long)m0 * K + t * KT;
        #pragma unroll
        for (int i = 0; i < 8; i++) {
            const int idx = tid + i * 256;
            const int row = idx >> 4, c4 = idx & 15;
            float4 v = *reinterpret_cast<const float4*>(Ag + (long long)row * K + c4 * 4);
            float hx = bf16_rn_f32(v.x), hy = bf16_rn_f32(v.y);
            float hz = bf16_rn_f32(v.z), hw = bf16_rn_f32(v.w);
            uint32_t off = (uint32_t)(row * 128 + c4 * 8);
            uint32_t sw  = off ^ ((off >> 3) & 0x70);
            uint64_t hi = ((uint64_t)pack_bf16(v.z, v.w) << 32) | pack_bf16(v.x, v.y);
            uint64_t lo = ((uint64_t)pack_bf16(v.z - hz, v.w - hw) << 32)
                        |  pack_bf16(v.x - hx, v.y - hy);
            asm volatile("st.shared.b64 [%0], %1;" :: "r"(bb + sw), "l"(hi) : "memory");
            asm volatile("st.shared.b64 [%0], %1;" :: "r"(bb + 16384 + sw), "l"(lo) : "memory");
        }
        // ---- load + split B tile: 128 rows x 64 k ----
        const float* Bg = B + (long long)n0 * K + t * KT;
        #pragma unroll
        for (int i = 0; i < 8; i++) {
            const int idx = tid + i * 256;
            const int row = idx >> 4, c4 = idx & 15;
            float4 v = *reinterpret_cast<const float4*>(Bg + (long long)row * K + c4 * 4);
            float hx = bf16_rn_f32(v.x), hy = bf16_rn_f32(v.y);
            float hz = bf16_rn_f32(v.z), hw = bf16_rn_f32(v.w);
            uint32_t off = (uint32_t)(row * 128 + c4 * 8);
            uint32_t sw  = off ^ ((off >> 3) & 0x70);
            uint64_t hi = ((uint64_t)pack_bf16(v.z, v.w) << 32) | pack_bf16(v.x, v.y);
            uint64_t lo = ((uint64_t)pack_bf16(v.z - hz, v.w - hw) << 32)
                        |  pack_bf16(v.x - hx, v.y - hy);
            asm volatile("st.shared.b64 [%0], %1;" :: "r"(bb + 32768 + sw), "l"(hi) : "memory");
            asm volatile("st.shared.b64 [%0], %1;" :: "r"(bb + 49152 + sw), "l"(lo) : "memory");
        }
        FENCE_ASYNC();
        __syncthreads();

        // ---- issue 12 MMAs (3 splits x 4 K-steps of 16) ----
        if (tid == 0) {
            uint64_t ah = mk_desc(bb);
            uint64_t al = mk_desc(bb + 16384);
            uint64_t bh = mk_desc(bb + 32768);
            uint64_t bl = mk_desc(bb + 49152);
            #pragma unroll
            for (int kc = 0; kc < 4; kc++)
                mma_f16_ss(tmem, ah + kc * 2, bh + kc * 2, IDESC, (t | kc) != 0);
            #pragma unroll
            for (int kc = 0; kc < 4; kc++)
                mma_f16_ss(tmem, ah + kc * 2, bl + kc * 2, IDESC, 1);
            #pragma unroll
            for (int kc = 0; kc < 4; kc++)
                mma_f16_ss(tmem, al + kc * 2, bh + kc * 2, IDESC, 1);
            TC_COMMIT(buf == 0 ? mbar0 : mbar1);
        }
    }

    // ---- drain: last commit covers all previously issued MMAs ----
    if (((nk - 1) & 1) == 0) { MBAR_WAIT(mbar0, ph0); }
    else                     { MBAR_WAIT(mbar1, ph1); }
    TC_FENCE_AFTER();

    if (HAS_BIAS) {
        if (tid < 128) ((float*)tilesg)[tid] = bias[n0 + tid];
        __syncthreads();
    }

    // ---- epilogue: warps 0-3 read TMEM 128x128 f32 and store ----
    if (tid < 128) {
        uint32_t d[128];
        TC_LD_X32(d +  0, tmem +  0);
        TC_LD_X32(d + 32, tmem + 32);
        TC_LD_X32(d + 64, tmem + 64);
        TC_LD_X32(d + 96, tmem + 96);
        TC_WAIT_LD();
        TC_FENCE_BEFORE();
        const int row = m0 + tid;
        float* cp = Cout + (long long)row * N + n0;
        const float* bsm = (const float*)tilesg;
        #pragma unroll
        for (int c = 0; c < 128; c += 4) {
            float4 o;
            o.x = __uint_as_float(d[c + 0]);
            o.y = __uint_as_float(d[c + 1]);
            o.z = __uint_as_float(d[c + 2]);
            o.w = __uint_as_float(d[c + 3]);
            if (HAS_BIAS) {
                o.x += bsm[c + 0]; o.y += bsm[c + 1];
                o.z += bsm[c + 2]; o.w += bsm[c + 3];
            }
            *reinterpret_cast<float4*>(cp + c) = o;
        }
    }

    __syncthreads();
    if (tid == 0) {
        asm volatile("mbarrier.inval.shared.b64 [%0];" :: "r"(mbar0) : "memory");
        asm volatile("mbarrier.inval.shared.b64 [%0];" :: "r"(mbar1) : "memory");
    }
    __syncthreads();
    if (tid < 32) { TC_RELINQ(); TC_DEALLOC(tmem, 128); }

#else
    // ======================= SIMT fp32 fallback (base target) ===============
    float (*As)[128] = reinterpret_cast<float (*)[128]>(smem);
    float (*Bs)[128] = reinterpret_cast<float (*)[128]>(smem + 4096);

    const int ty = tid >> 4;           // 0..15
    const int tx = tid & 15;           // 0..15
    const int aRow = tid >> 1;         // 0..127
    const int aCol = (tid & 1) * 4;    // 0 or 4

    float acc[8][8] = {};

    for (int k0 = 0; k0 < K; k0 += 8) {
        float4 av = *reinterpret_cast<const float4*>(
            &A[(long long)(m0 + aRow) * K + (k0 + aCol)]);
        As[aCol + 0][aRow] = av.x;
        As[aCol + 1][aRow] = av.y;
        As[aCol + 2][aRow] = av.z;
        As[aCol + 3][aRow] = av.w;

        float4 bv = *reinterpret_cast<const float4*>(
            &B[(long long)(n0 + aRow) * K + (k0 + aCol)]);
        Bs[aCol + 0][aRow] = bv.x;
        Bs[aCol + 1][aRow] = bv.y;
        Bs[aCol + 2][aRow] = bv.z;
        Bs[aCol + 3][aRow] = bv.w;
        __syncthreads();

        #pragma unroll
        for (int kk = 0; kk < 8; kk++) {
            float ra[8], rb[8];
            #pragma unroll
            for (int i = 0; i < 8; i++) ra[i] = As[kk][ty * 8 + i];
            #pragma unroll
            for (int j = 0; j < 8; j++) rb[j] = Bs[kk][tx * 8 + j];
            #pragma unroll
            for (int i = 0; i < 8; i++)
                #pragma unroll
                for (int j = 0; j < 8; j++)
                    acc[i][j] = fmaf(ra[i], rb[j], acc[i][j]);
        }
        __syncthreads();
    }

    #pragma unroll
    for (int i = 0; i < 8; i++) {
        const long long row = m0 + ty * 8 + i;
        float* cp = &Cout[row * N + n0 + tx * 8];
        float4 o0, o1;
        o0.x = acc[i][0]; o0.y = acc[i][1]; o0.z = acc[i][2]; o0.w = acc[i][3];
        o1.x = acc[i][4]; o1.y = acc[i][5]; o1.z = acc[i][6]; o1.w = acc[i][7];
        if (HAS_BIAS) {
            const float* bp = &bias[n0 + tx * 8];
            o0.x += bp[0]; o0.y += bp[1]; o0.z += bp[2]; o0.w += bp[3];
            o1.x += bp[4]; o1.y += bp[5]; o1.z += bp[6]; o1.w += bp[7];
        }
        reinterpret_cast<float4*>(cp)[0] = o0;
        reinterpret_cast<float4*>(cp)[1] = o1;
    }
#endif
}

// ---------------------------------------------------------------------------
// 32x32 tiled transpose: out[c][r] = in[r][c]   (per batch z)
// ---------------------------------------------------------------------------
__global__ __launch_bounds__(256)
void transpose_k(const float* __restrict__ in, float* __restrict__ out,
                 int R, int Cc, long long sIn, long long sOut)
{
    __shared__ float t[32][33];
    in  += (long long)blockIdx.z * sIn;
    out += (long long)blockIdx.z * sOut;
    const int r0 = blockIdx.y * 32, c0 = blockIdx.x * 32;
    const int tx = threadIdx.x & 31, ty = threadIdx.x >> 5;
    #pragma unroll
    for (int i = 0; i < 32; i += 8)
        t[ty + i][tx] = in[(long long)(r0 + ty + i) * Cc + c0 + tx];
    __syncthreads();
    #pragma unroll
    for (int i = 0; i < 32; i += 8)
        out[(long long)(c0 + ty + i) * R + r0 + tx] = t[tx][ty + i];
}

// ---------------------------------------------------------------------------
// Row softmax, rows of 4096, pre-scale folded into exp.
// ---------------------------------------------------------------------------
__global__ __launch_bounds__(256)
void softmax_k(float* __restrict__ S, float scale)
{
    float* row = S + (long long)blockIdx.x * 4096;
    const int t = threadIdx.x;
    __shared__ float red[256];

    float vals[16];
    float m = -1e30f;
    #pragma unroll
    for (int i = 0; i < 16; i++) {
        vals[i] = row[t + i * 256];
        m = fmaxf(m, vals[i]);
    }
    red[t] = m;
    __syncthreads();
    #pragma unroll
    for (int s = 128; s > 0; s >>= 1) {
        if (t < s) red[t] = fmaxf(red[t], red[t + s]);
        __syncthreads();
    }
    m = red[0];
    __syncthreads();

    float sum = 0.f;
    #pragma unroll
    for (int i = 0; i < 16; i++) {
        vals[i] = __expf(scale * (vals[i] - m));
        sum += vals[i];
    }
    red[t] = sum;
    __syncthreads();
    #pragma unroll
    for (int s = 128; s > 0; s >>= 1) {
        if (t < s) red[t] += red[t + s];
        __syncthreads();
    }
    const float inv = 1.0f / red[0];
    #pragma unroll
    for (int i = 0; i < 16; i++)
        row[t + i * 256] = vals[i] * inv;
}

// ---------------------------------------------------------------------------
extern "C" void kernel_launch(void* const* d_in, const int* in_sizes, int n_in,
                              void* d_out, int out_size)
{
    const float* x  = (const float*)d_in[0];
    const float* Wq = (const float*)d_in[1];
    const float* bq = (const float*)d_in[2];
    const float* Wk = (const float*)d_in[3];
    const float* bk = (const float*)d_in[4];
    const float* Wv = (const float*)d_in[5];
    const float* bv = (const float*)d_in[6];
    const float* Wo = (const float*)d_in[7];
    const float* bo = (const float*)d_in[8];
    float* out = (float*)d_out;

    const int M = NB * NSEQ;                 // 16384
    const float scale = 0.03125f;            // 1024^-0.5

    float *q, *k, *v, *vt, *s, *ao, *wt;
    cudaGetSymbolAddress((void**)&q,  g_q);
    cudaGetSymbolAddress((void**)&k,  g_k);
    cudaGetSymbolAddress((void**)&v,  g_v);
    cudaGetSymbolAddress((void**)&vt, g_vt);
    cudaGetSymbolAddress((void**)&s,  g_s);
    cudaGetSymbolAddress((void**)&ao, g_ao);
    cudaGetSymbolAddress((void**)&wt, g_wt);

    cudaFuncSetAttribute((const void*)tc_gemm<true>,
                         cudaFuncAttributeMaxDynamicSharedMemorySize, SMEM_BYTES);
    cudaFuncSetAttribute((const void*)tc_gemm<false>,
                         cudaFuncAttributeMaxDynamicSharedMemorySize, SMEM_BYTES);

    const long long qkv = (long long)NSEQ * DIMC;
    const long long ss  = (long long)NSEQ * NSEQ;

    dim3 b256(256);

    // 1) transpose weights -> wt (WqT, WkT, WvT, WoT)
    {
        dim3 g(32, 32, 1);
        transpose_k<<<g, b256>>>(Wq, wt + 0 * 1048576, DIMC, DIMC, 0, 0);
        transpose_k<<<g, b256>>>(Wk, wt + 1 * 1048576, DIMC, DIMC, 0, 0);
        transpose_k<<<g, b256>>>(Wv, wt + 2 * 1048576, DIMC, DIMC, 0, 0);
        transpose_k<<<g, b256>>>(Wo, wt + 3 * 1048576, DIMC, DIMC, 0, 0);
    }

    // 2) q, k, v projections: [16384,1024] x [1024,1024]^T + bias
    {
        dim3 g(DIMC / 128, M / 128, 1);
        tc_gemm<true><<<g, b256, SMEM_BYTES>>>(x, wt + 0 * 1048576, bq, q, M, DIMC, DIMC, 0, 0, 0);
        tc_gemm<true><<<g, b256, SMEM_BYTES>>>(x, wt + 1 * 1048576, bk, k, M, DIMC, DIMC, 0, 0, 0);
        tc_gemm<true><<<g, b256, SMEM_BYTES>>>(x, wt + 2 * 1048576, bv, v, M, DIMC, DIMC, 0, 0, 0);
    }

    // 3) vT[b] = v[b]^T  ([4096,1024] -> [1024,4096])
    {
        dim3 g(DIMC / 32, NSEQ / 32, NB);
        transpose_k<<<g, b256>>>(v, vt, NSEQ, DIMC, qkv, qkv);
    }

    // 4) scores[b] = q[b] @ k[b]^T
    {
        dim3 g(NSEQ / 128, NSEQ / 128, NB);
        tc_gemm<false><<<g, b256, SMEM_BYTES>>>(q, k, nullptr, s,
                                                NSEQ, NSEQ, DIMC, qkv, qkv, ss);
    }

    // 5) softmax rows
    softmax_k<<<M, b256>>>(s, scale);

    // 6) ao[b] = attn[b] @ vT[b]^T  (K = 4096)
    {
        dim3 g(DIMC / 128, NSEQ / 128, NB);
        tc_gemm<false><<<g, b256, SMEM_BYTES>>>(s, vt, nullptr, ao,
                                                NSEQ, DIMC, NSEQ, ss, qkv, qkv);
    }

    // 7) out = ao @ WoT^T + bo
    {
        dim3 g(DIMC / 128, M / 128, 1);
        tc_gemm<true><<<g, b256, SMEM_BYTES>>>(ao, wt + 3 * 1048576, bo, out,
                                               M, DIMC, DIMC, 0, 0, 0);
    }
}